// round 1
// baseline (speedup 1.0000x reference)
#include <cuda_runtime.h>
#include <cstdint>

// Shapes (fixed by the problem instance)
#define B_  4
#define H_  96
#define W_  96
#define D_  96
#define C_  32
#define WH 8
#define NWH 12            // 96/8
#define NUM_WIN 1728      // 12*12*12
#define LEN_KEEP 691      // int(1728*0.4)
#define ELEMS_PER_OUT (B_*H_*W_*D_*C_)   // 113,246,208 floats

// window mask: 1 = masked, 0 = kept
__device__ float g_winmask[B_ * NUM_WIN];

// ---------------------------------------------------------------------------
// Kernel 1: compute per-window keep/mask via rank (stable-argsort equivalent).
// grid = (B_, 4), blockDim = 432. Each block loads the batch's 1728 noise
// values to SMEM; each thread ranks one window.
// ---------------------------------------------------------------------------
__global__ void winmask_kernel(const float* __restrict__ noise) {
    __shared__ float sn[NUM_WIN];
    const int b = blockIdx.x;
    const float* nb = noise + b * NUM_WIN;
    for (int i = threadIdx.x; i < NUM_WIN; i += blockDim.x)
        sn[i] = nb[i];
    __syncthreads();

    const int i = blockIdx.y * 432 + threadIdx.x;   // 4*432 = 1728
    const float v = sn[i];
    int rank = 0;
#pragma unroll 4
    for (int j = 0; j < NUM_WIN; j++) {
        const float u = sn[j];
        // stable sort tie-break: earlier index wins on equality
        rank += (u < v) || (u == v && j < i);
    }
    g_winmask[b * NUM_WIN + i] = (rank < LEN_KEEP) ? 0.0f : 1.0f;
}

// ---------------------------------------------------------------------------
// Kernel 2: expand window mask to voxels, write x_masked and mask.
// One float4 per thread. voxel layout: (((b*H + h)*W + w)*D + d)*C + c,
// C=32 floats = 8 float4s per voxel -> voxel = idx4 >> 3.
// ---------------------------------------------------------------------------
__global__ void __launch_bounds__(256)
mask_expand_kernel(const float4* __restrict__ x,
                   float4* __restrict__ out_xm,
                   float4* __restrict__ out_mk) {
    const long long idx4 = (long long)blockIdx.x * blockDim.x + threadIdx.x;
    // total float4s = ELEMS_PER_OUT/4 = 28,311,552 ; grid sized exactly
    const int voxel = (int)(idx4 >> 3);
    const int d  = voxel % D_;
    int rest     = voxel / D_;
    const int w  = rest % W_;
    rest         = rest / W_;
    const int h  = rest % H_;
    const int b  = rest / H_;

    const int win = ((b * NWH + (h >> 3)) * NWH + (w >> 3)) * NWH + (d >> 3);
    const float m = __ldg(&g_winmask[win]);
    const float keep = 1.0f - m;

    const float4 v = x[idx4];
    float4 xm;
    xm.x = v.x * keep; xm.y = v.y * keep; xm.z = v.z * keep; xm.w = v.w * keep;
    out_xm[idx4] = xm;
    out_mk[idx4] = make_float4(m, m, m, m);
}

extern "C" void kernel_launch(void* const* d_in, const int* in_sizes, int n_in,
                              void* d_out, int out_size) {
    const float* x     = (const float*)d_in[0];   // [B,H,W,D,C] fp32
    const float* noise = (const float*)d_in[1];   // [B, 1728]   fp32
    float* out = (float*)d_out;                   // [x_masked | mask]

    // Kernel 1: window masks (~5 us)
    {
        dim3 grid(B_, 4);
        winmask_kernel<<<grid, 432>>>(noise);
    }

    // Kernel 2: expand + apply (~225 us, HBM bound)
    {
        const long long n4 = (long long)ELEMS_PER_OUT / 4;  // 28,311,552
        const int threads = 256;
        const long long blocks = n4 / threads;              // 110,592 exactly
        mask_expand_kernel<<<(unsigned)blocks, threads>>>(
            (const float4*)x,
            (float4*)out,
            (float4*)(out + (long long)ELEMS_PER_OUT));
    }
}

// round 2
// speedup vs baseline: 1.3182x; 1.3182x over previous
#include <cuda_runtime.h>
#include <cstdint>

// Shapes (fixed by the problem instance)
#define B_  4
#define H_  96
#define W_  96
#define D_  96
#define C_  32
#define NWH 12            // 96/8
#define NUM_WIN 1728      // 12*12*12
#define LEN_KEEP 691      // int(1728*0.4)
#define ELEMS_PER_OUT (B_*H_*W_*D_*C_)   // 113,246,208 floats

// window mask: 1 = masked, 0 = kept
__device__ float g_winmask[B_ * NUM_WIN];

// ---------------------------------------------------------------------------
// Kernel 1: per-window keep/mask via stable rank. 4 threads per window index,
// each ranking over a 432-element chunk of j, combined via shfl.
// grid = (B_, 27), block = 256: each block covers 64 window indices.
// ---------------------------------------------------------------------------
__global__ void __launch_bounds__(256)
winmask_kernel(const float* __restrict__ noise) {
    __shared__ float sn[NUM_WIN];
    const int b = blockIdx.x;
    const float* nb = noise + b * NUM_WIN;
    for (int t = threadIdx.x; t < NUM_WIN; t += 256)
        sn[t] = nb[t];
    __syncthreads();

    const int i      = blockIdx.y * 64 + (threadIdx.x >> 2);  // window index
    const int jchunk = threadIdx.x & 3;
    const float v = sn[i];

    int rank = 0;
    const int j0 = jchunk * 432;
#pragma unroll 4
    for (int j = j0; j < j0 + 432; j++) {
        const float u = sn[j];
        // stable-argsort tie-break: earlier index wins on equality
        rank += (u < v) || (u == v && j < i);
    }
    // sum across the 4 adjacent lanes handling this i
    rank += __shfl_xor_sync(0xFFFFFFFFu, rank, 1);
    rank += __shfl_xor_sync(0xFFFFFFFFu, rank, 2);

    if (jchunk == 0)
        g_winmask[b * NUM_WIN + i] = (rank < LEN_KEEP) ? 0.0f : 1.0f;
}

// ---------------------------------------------------------------------------
// Kernel 2: expand window mask to voxels, write x_masked and mask.
// One block per (b,h,w) row: 96 voxels * 32 floats = 768 float4s; 256 threads
// do 3 float4s each. Window index within the row is (float4_idx >> 6) —
// warp-uniform, so the load of x is skipped divergence-free for masked
// windows (60% of traffic).
// ---------------------------------------------------------------------------
__global__ void __launch_bounds__(256)
mask_expand_kernel(const float4* __restrict__ x,
                   float4* __restrict__ out_xm,
                   float4* __restrict__ out_mk) {
    const int row = blockIdx.x;               // b*H*W + h*W + w
    const int w   = row % W_;
    const int hb  = row / W_;
    const int h   = hb % H_;
    const int b   = hb / H_;
    const int winbase = ((b * NWH + (h >> 3)) * NWH + (w >> 3)) * NWH;

    const long long base = (long long)row * 768;   // float4 offset of this row
    const float4* xr = x + base;
    float4* xmr = out_xm + base;
    float4* mkr = out_mk + base;

#pragma unroll
    for (int k = 0; k < 3; k++) {
        const int i = threadIdx.x + k * 256;       // 0..767
        const float m = g_winmask[winbase + (i >> 6)];  // warp-uniform, L1-hit
        float4 o = make_float4(0.f, 0.f, 0.f, 0.f);
        if (m == 0.0f) {
            o = xr[i];                              // only kept windows read x
        }
        xmr[i] = o;
        mkr[i] = make_float4(m, m, m, m);
    }
}

extern "C" void kernel_launch(void* const* d_in, const int* in_sizes, int n_in,
                              void* d_out, int out_size) {
    const float* x     = (const float*)d_in[0];   // [B,H,W,D,C] fp32
    const float* noise = (const float*)d_in[1];   // [B, 1728]   fp32
    float* out = (float*)d_out;                   // [x_masked | mask]

    {
        dim3 grid(B_, 27);
        winmask_kernel<<<grid, 256>>>(noise);
    }
    {
        const int rows = B_ * H_ * W_;            // 36864
        mask_expand_kernel<<<rows, 256>>>(
            (const float4*)x,
            (float4*)out,
            (float4*)(out + (long long)ELEMS_PER_OUT));
    }
}